// round 1
// baseline (speedup 1.0000x reference)
#include <cuda_runtime.h>

// Problem dims
// C=64, S=256, T=500, N=2000
// Output layout (concatenated, float32):
//   log_obs    [T,N]      at offset 0            (1,000,000)
//   log_obs_   [T,C,N]    at offset 1,000,000    (64,000,000)
//   log_hidden [T,C,S]    at offset 65,000,000   (8,192,000)

static __device__ float g_Ppow[16 * 256 * 256];   // g_Ppow[i] = P^(i+1)
static __device__ float g_p[500 * 64 * 256];      // probabilities p_t  [T][C][S]
static __device__ float g_E[256 * 2000];          // E, then Ee = exp(log_E - colmax) in place
static __device__ float g_bmaxE[2048];            // colmax of log_E (= log colmax of E)
static __device__ float g_w[500 * 64];            // softmax chain weights

// ---------------- block reductions ----------------
__device__ __forceinline__ float bredMax(float v) {
    __shared__ float sm[8];
    unsigned nw = blockDim.x >> 5;
#pragma unroll
    for (int o = 16; o; o >>= 1) v = fmaxf(v, __shfl_xor_sync(0xffffffffu, v, o));
    if ((threadIdx.x & 31) == 0) sm[threadIdx.x >> 5] = v;
    __syncthreads();
    if (threadIdx.x < 32) {
        v = (threadIdx.x < nw) ? sm[threadIdx.x] : -3.402823e38f;
#pragma unroll
        for (int o = 4; o; o >>= 1) v = fmaxf(v, __shfl_xor_sync(0xffffffffu, v, o));
        if (threadIdx.x == 0) sm[0] = v;
    }
    __syncthreads();
    v = sm[0];
    __syncthreads();
    return v;
}

__device__ __forceinline__ float bredSum(float v) {
    __shared__ float sm[8];
    unsigned nw = blockDim.x >> 5;
#pragma unroll
    for (int o = 16; o; o >>= 1) v += __shfl_xor_sync(0xffffffffu, v, o);
    if ((threadIdx.x & 31) == 0) sm[threadIdx.x >> 5] = v;
    __syncthreads();
    if (threadIdx.x < 32) {
        v = (threadIdx.x < nw) ? sm[threadIdx.x] : 0.f;
#pragma unroll
        for (int o = 4; o; o >>= 1) v += __shfl_xor_sync(0xffffffffu, v, o);
        if (threadIdx.x == 0) sm[0] = v;
    }
    __syncthreads();
    v = sm[0];
    __syncthreads();
    return v;
}

// ---------------- preprocessing ----------------
// P = softmax rows of utm [256,256] -> g_Ppow[0]
__global__ void k_softmax_P(const float* __restrict__ x) {
    int r = blockIdx.x;
    float v = x[r * 256 + threadIdx.x];
    float m = bredMax(v);
    float e = __expf(v - m);
    float Z = bredSum(e);
    g_Ppow[r * 256 + threadIdx.x] = e / Z;
}

// p0 = softmax rows of usi [64,256] -> g_p[0], and exact log-softmax to hidden[t=0]
__global__ void k_softmax_p0(const float* __restrict__ x, float* __restrict__ hid) {
    int r = blockIdx.x;
    float v = x[r * 256 + threadIdx.x];
    float m = bredMax(v);
    float e = __expf(v - m);
    float Z = bredSum(e);
    g_p[r * 256 + threadIdx.x] = e / Z;
    hid[r * 256 + threadIdx.x] = (v - m) - __logf(Z);
}

// w = softmax rows of ucw [500,64]
__global__ void k_softmax_w(const float* __restrict__ x) {
    int r = blockIdx.x;
    float v = x[r * 64 + threadIdx.x];
    float m = bredMax(v);
    float e = __expf(v - m);
    float Z = bredSum(e);
    g_w[r * 64 + threadIdx.x] = e / Z;
}

// E rows: masked softmax of uem rows [256 x 2000] -> g_E (probability domain)
__global__ void k_Erow(const float* __restrict__ x, const float* __restrict__ mask) {
    int s = blockIdx.x;
    const float* xr = x + (size_t)s * 2000;
    const float* mr = mask + (size_t)s * 2000;
    float* Er = g_E + (size_t)s * 2000;
    float m = -3.402823e38f;
    for (int n = threadIdx.x; n < 2000; n += 256)
        if (mr[n] > 0.f) m = fmaxf(m, xr[n]);
    m = bredMax(m);
    float sloc = 0.f;
    for (int n = threadIdx.x; n < 2000; n += 256) {
        float e = (mr[n] > 0.f) ? __expf(xr[n] - m) * mr[n] : 0.f;
        Er[n] = e;
        sloc += e;
    }
    float Z = bredSum(sloc);
    float inv = 1.f / Z;
    for (int n = threadIdx.x; n < 2000; n += 256) Er[n] *= inv;
}

// Column max of E over S; Ee = E/colmax (in place), bmaxE = log(colmax)
__global__ void k_Ecol() {
    int n = blockIdx.x * 256 + threadIdx.x;
    if (n >= 2000) return;
    float m = 0.f;
    for (int s = 0; s < 256; s++) m = fmaxf(m, g_E[(size_t)s * 2000 + n]);
    g_bmaxE[n] = __logf(m);
    float inv = 1.f / m;
    for (int s = 0; s < 256; s++) g_E[(size_t)s * 2000 + n] *= inv;
}

// ---------------- P power chain: g_Ppow[k] = g_Ppow[k-1] @ P ----------------
__global__ __launch_bounds__(256) void k_pmm(int k) {
    __shared__ float As[64][68];
    __shared__ float Bs[64][68];
    const float* A = g_Ppow + (size_t)(k - 1) * 65536;
    const float* B = g_Ppow;  // P
    float* Cm = g_Ppow + (size_t)k * 65536;
    const int u = threadIdx.x;
    const int tx = u & 15, ty = u >> 4;
    const int r0 = blockIdx.y * 64, c0 = blockIdx.x * 64;
    float acc[4][4];
#pragma unroll
    for (int i = 0; i < 4; i++)
#pragma unroll
        for (int j = 0; j < 4; j++) acc[i][j] = 0.f;
    for (int k0 = 0; k0 < 256; k0 += 64) {
#pragma unroll
        for (int q = 0; q < 4; q++) {
            int f = q * 256 + u;
            int row = f >> 4, kq = (f & 15) << 2;
            *(float4*)&As[row][kq] = *(const float4*)&A[(size_t)(r0 + row) * 256 + k0 + kq];
            *(float4*)&Bs[row][kq] = *(const float4*)&B[(size_t)(k0 + row) * 256 + c0 + kq];
        }
        __syncthreads();
#pragma unroll
        for (int k2 = 0; k2 < 64; k2++) {
            float a0 = As[ty * 4 + 0][k2], a1 = As[ty * 4 + 1][k2];
            float a2 = As[ty * 4 + 2][k2], a3 = As[ty * 4 + 3][k2];
            float4 b = *(const float4*)&Bs[k2][tx * 4];
            acc[0][0] += a0 * b.x; acc[0][1] += a0 * b.y; acc[0][2] += a0 * b.z; acc[0][3] += a0 * b.w;
            acc[1][0] += a1 * b.x; acc[1][1] += a1 * b.y; acc[1][2] += a1 * b.z; acc[1][3] += a1 * b.w;
            acc[2][0] += a2 * b.x; acc[2][1] += a2 * b.y; acc[2][2] += a2 * b.z; acc[2][3] += a2 * b.w;
            acc[3][0] += a3 * b.x; acc[3][1] += a3 * b.y; acc[3][2] += a3 * b.z; acc[3][3] += a3 * b.w;
        }
        __syncthreads();
    }
#pragma unroll
    for (int i = 0; i < 4; i++) {
        float4 v = make_float4(acc[i][0], acc[i][1], acc[i][2], acc[i][3]);
        *(float4*)&Cm[(size_t)(r0 + ty * 4 + i) * 256 + c0 + tx * 4] = v;
    }
}

// ---------------- superstep: p_{base+i} = p_base @ P^i, i = 1..gridDim.y ----------------
__global__ __launch_bounds__(256) void k_superstep(int base, float* __restrict__ hid) {
    __shared__ float As[64][68];
    __shared__ float Bs[64][68];
    const int u = threadIdx.x;
    const int tx = u & 15, ty = u >> 4;
    const int i = blockIdx.y + 1;
    const int c0 = blockIdx.x * 64;
    const float* A = g_p + (size_t)base * (64 * 256);
    const float* B = g_Ppow + (size_t)(i - 1) * 65536;
    float acc[4][4];
#pragma unroll
    for (int a = 0; a < 4; a++)
#pragma unroll
        for (int b = 0; b < 4; b++) acc[a][b] = 0.f;
    for (int k0 = 0; k0 < 256; k0 += 64) {
#pragma unroll
        for (int q = 0; q < 4; q++) {
            int f = q * 256 + u;
            int row = f >> 4, kq = (f & 15) << 2;
            *(float4*)&As[row][kq] = *(const float4*)&A[(size_t)row * 256 + k0 + kq];
            *(float4*)&Bs[row][kq] = *(const float4*)&B[(size_t)(k0 + row) * 256 + c0 + kq];
        }
        __syncthreads();
#pragma unroll
        for (int k2 = 0; k2 < 64; k2++) {
            float a0 = As[ty * 4 + 0][k2], a1 = As[ty * 4 + 1][k2];
            float a2 = As[ty * 4 + 2][k2], a3 = As[ty * 4 + 3][k2];
            float4 b = *(const float4*)&Bs[k2][tx * 4];
            acc[0][0] += a0 * b.x; acc[0][1] += a0 * b.y; acc[0][2] += a0 * b.z; acc[0][3] += a0 * b.w;
            acc[1][0] += a1 * b.x; acc[1][1] += a1 * b.y; acc[1][2] += a1 * b.z; acc[1][3] += a1 * b.w;
            acc[2][0] += a2 * b.x; acc[2][1] += a2 * b.y; acc[2][2] += a2 * b.z; acc[2][3] += a2 * b.w;
            acc[3][0] += a3 * b.x; acc[3][1] += a3 * b.y; acc[3][2] += a3 * b.z; acc[3][3] += a3 * b.w;
        }
        __syncthreads();
    }
    const int t = base + i;
    float* pout = g_p + (size_t)t * (64 * 256);
    float* hout = hid + (size_t)t * (64 * 256);
#pragma unroll
    for (int a = 0; a < 4; a++) {
        size_t idx = (size_t)(ty * 4 + a) * 256 + c0 + tx * 4;
        float4 v = make_float4(acc[a][0], acc[a][1], acc[a][2], acc[a][3]);
        *(float4*)&pout[idx] = v;
        float4 lg = make_float4(__logf(v.x), __logf(v.y), __logf(v.z), __logf(v.w));
        *(float4*)&hout[idx] = lg;
    }
}

// ---------------- emission: Q = p[t] @ Ee, log_obs_ and log_obs ----------------
__global__ __launch_bounds__(256) void k_emis(float* __restrict__ out) {
    __shared__ float As[64][36];    // p[t] chunk  [64 x 32]
    __shared__ float Bs[32][132];   // Ee chunk    [32 x 128]
    __shared__ float w_sm[64];
    const int u = threadIdx.x;
    const int tx = u & 15, ty = u >> 4;
    const int t = blockIdx.y;
    const int n0 = blockIdx.x * 128;
    if (u < 64) w_sm[u] = g_w[t * 64 + u];
    const float* Ap = g_p + (size_t)t * (64 * 256);
    float acc[4][8];
#pragma unroll
    for (int i = 0; i < 4; i++)
#pragma unroll
        for (int j = 0; j < 8; j++) acc[i][j] = 0.f;

    for (int k0 = 0; k0 < 256; k0 += 32) {
#pragma unroll
        for (int q = 0; q < 2; q++) {
            int f = q * 256 + u;
            int row = f >> 3, kq = (f & 7) << 2;
            *(float4*)&As[row][kq] = *(const float4*)&Ap[(size_t)row * 256 + k0 + kq];
        }
#pragma unroll
        for (int q = 0; q < 4; q++) {
            int f = q * 256 + u;
            int row = f >> 5, nq = (f & 31) << 2;
            int n = n0 + nq;
            float4 v;
            if (n < 2000) v = *(const float4*)&g_E[(size_t)(k0 + row) * 2000 + n];
            else v = make_float4(0.f, 0.f, 0.f, 0.f);
            *(float4*)&Bs[row][nq] = v;
        }
        __syncthreads();
#pragma unroll
        for (int k2 = 0; k2 < 32; k2++) {
            float a0 = As[ty * 4 + 0][k2], a1 = As[ty * 4 + 1][k2];
            float a2 = As[ty * 4 + 2][k2], a3 = As[ty * 4 + 3][k2];
            float4 bl = *(const float4*)&Bs[k2][tx * 8];
            float4 bh = *(const float4*)&Bs[k2][tx * 8 + 4];
            acc[0][0] += a0 * bl.x; acc[0][1] += a0 * bl.y; acc[0][2] += a0 * bl.z; acc[0][3] += a0 * bl.w;
            acc[0][4] += a0 * bh.x; acc[0][5] += a0 * bh.y; acc[0][6] += a0 * bh.z; acc[0][7] += a0 * bh.w;
            acc[1][0] += a1 * bl.x; acc[1][1] += a1 * bl.y; acc[1][2] += a1 * bl.z; acc[1][3] += a1 * bl.w;
            acc[1][4] += a1 * bh.x; acc[1][5] += a1 * bh.y; acc[1][6] += a1 * bh.z; acc[1][7] += a1 * bh.w;
            acc[2][0] += a2 * bl.x; acc[2][1] += a2 * bl.y; acc[2][2] += a2 * bl.z; acc[2][3] += a2 * bl.w;
            acc[2][4] += a2 * bh.x; acc[2][5] += a2 * bh.y; acc[2][6] += a2 * bh.z; acc[2][7] += a2 * bh.w;
            acc[3][0] += a3 * bl.x; acc[3][1] += a3 * bl.y; acc[3][2] += a3 * bl.z; acc[3][3] += a3 * bl.w;
            acc[3][4] += a3 * bh.x; acc[3][5] += a3 * bh.y; acc[3][6] += a3 * bh.z; acc[3][7] += a3 * bh.w;
        }
        __syncthreads();
    }
    const int nbase = n0 + tx * 8;
    const bool valid = nbase < 2000;
    float bm[8];
#pragma unroll
    for (int j = 0; j < 8; j++) bm[j] = valid ? g_bmaxE[nbase + j] : 0.f;

    float* obsp = out + 1000000u;  // log_obs_ region
    if (valid) {
#pragma unroll
        for (int i = 0; i < 4; i++) {
            int r = ty * 4 + i;
            size_t o = (size_t)(t * 64 + r) * 2000 + nbase;
            float4 lo = make_float4(__logf(acc[i][0]) + bm[0], __logf(acc[i][1]) + bm[1],
                                    __logf(acc[i][2]) + bm[2], __logf(acc[i][3]) + bm[3]);
            float4 hi = make_float4(__logf(acc[i][4]) + bm[4], __logf(acc[i][5]) + bm[5],
                                    __logf(acc[i][6]) + bm[6], __logf(acc[i][7]) + bm[7]);
            *(float4*)&obsp[o] = lo;
            *(float4*)&obsp[o + 4] = hi;
        }
    }
    // weighted sum over c for log_obs
    float ps[8];
#pragma unroll
    for (int j = 0; j < 8; j++) {
        float s = 0.f;
#pragma unroll
        for (int i = 0; i < 4; i++) s += w_sm[ty * 4 + i] * acc[i][j];
        ps[j] = s;
    }
    float* red = &As[0][0];  // reuse (16*128 = 2048 <= 64*36 floats)
#pragma unroll
    for (int j = 0; j < 8; j++) red[ty * 128 + tx * 8 + j] = ps[j];
    __syncthreads();
#pragma unroll
    for (int h = 8; h > 0; h >>= 1) {
        if (ty < h) {
#pragma unroll
            for (int j = 0; j < 8; j++)
                red[ty * 128 + tx * 8 + j] += red[(ty + h) * 128 + tx * 8 + j];
        }
        __syncthreads();
    }
    if (ty == 0 && valid) {
#pragma unroll
        for (int j = 0; j < 8; j++)
            out[(size_t)t * 2000 + nbase + j] = __logf(red[tx * 8 + j]) + bm[j];
    }
}

// ---------------- launch ----------------
extern "C" void kernel_launch(void* const* d_in, const int* in_sizes, int n_in,
                              void* d_out, int out_size) {
    const float* usi = (const float*)d_in[0];  // [64,256]
    const float* ucw = (const float*)d_in[1];  // [500,64]
    const float* uem = (const float*)d_in[2];  // [256,2000]
    const float* utm = (const float*)d_in[3];  // [256,256]
    const float* msk = (const float*)d_in[4];  // [256,2000]
    float* out = (float*)d_out;
    float* hid = out + 65000000u;  // log_hidden region

    k_softmax_P<<<256, 256>>>(utm);
    k_softmax_p0<<<64, 256>>>(usi, hid);
    k_softmax_w<<<500, 64>>>(ucw);
    k_Erow<<<256, 256>>>(uem, msk);
    k_Ecol<<<8, 256>>>();

    for (int k = 1; k <= 15; k++)
        k_pmm<<<dim3(4, 4), 256>>>(k);

    for (int j = 0; j < 32; j++) {
        int base = j * 16;
        int nI = (j < 31) ? 16 : 3;  // covers t = 1..499
        k_superstep<<<dim3(4, nI), 256>>>(base, hid);
    }

    k_emis<<<dim3(16, 500), 256>>>(out);
}

// round 3
// speedup vs baseline: 2.8645x; 2.8645x over previous
#include <cuda_runtime.h>
#include <cstdint>

// Problem dims: C=64, S=256, T=500, N=2000
// Output layout (concatenated, float32):
//   log_obs    [T,N]      at offset 0            (1,000,000)
//   log_obs_   [T,C,N]    at offset 1,000,000    (64,000,000)
//   log_hidden [T,C,S]    at offset 65,000,000   (8,192,000)

static __device__ float g_Ppow[64 * 256 * 256];   // g_Ppow[i] = P^(i+1), i=0..63
static __device__ float g_p[500 * 64 * 256];      // probabilities p_t  [T][C][S]
static __device__ float g_E[256 * 2000];          // E, then Ee = E/colmax in place
static __device__ float g_Et[2048 * 256];         // Ee transposed [N_pad][S], zero padded
static __device__ float g_bmaxE[2048];            // log(colmax of E)
static __device__ float g_w[500 * 64];            // softmax chain weights
static __device__ float g_wp[500 * 256];          // wp[t,s] = sum_c w[t,c] p_t[c,s]

// ================= block reductions =================
__device__ __forceinline__ float bredMax(float v) {
    __shared__ float sm[8];
    unsigned nw = blockDim.x >> 5;
#pragma unroll
    for (int o = 16; o; o >>= 1) v = fmaxf(v, __shfl_xor_sync(0xffffffffu, v, o));
    if ((threadIdx.x & 31) == 0) sm[threadIdx.x >> 5] = v;
    __syncthreads();
    if (threadIdx.x < 32) {
        v = (threadIdx.x < nw) ? sm[threadIdx.x] : -3.402823e38f;
#pragma unroll
        for (int o = 4; o; o >>= 1) v = fmaxf(v, __shfl_xor_sync(0xffffffffu, v, o));
        if (threadIdx.x == 0) sm[0] = v;
    }
    __syncthreads();
    v = sm[0];
    __syncthreads();
    return v;
}
__device__ __forceinline__ float bredSum(float v) {
    __shared__ float sm[8];
    unsigned nw = blockDim.x >> 5;
#pragma unroll
    for (int o = 16; o; o >>= 1) v += __shfl_xor_sync(0xffffffffu, v, o);
    if ((threadIdx.x & 31) == 0) sm[threadIdx.x >> 5] = v;
    __syncthreads();
    if (threadIdx.x < 32) {
        v = (threadIdx.x < nw) ? sm[threadIdx.x] : 0.f;
#pragma unroll
        for (int o = 4; o; o >>= 1) v += __shfl_xor_sync(0xffffffffu, v, o);
        if (threadIdx.x == 0) sm[0] = v;
    }
    __syncthreads();
    v = sm[0];
    __syncthreads();
    return v;
}

// ================= preprocessing =================
__global__ void k_softmax_P(const float* __restrict__ x) {
    int r = blockIdx.x;
    float v = x[r * 256 + threadIdx.x];
    float m = bredMax(v);
    float e = __expf(v - m);
    float Z = bredSum(e);
    g_Ppow[r * 256 + threadIdx.x] = e / Z;
}
__global__ void k_softmax_p0(const float* __restrict__ x, float* __restrict__ hid) {
    int r = blockIdx.x;
    float v = x[r * 256 + threadIdx.x];
    float m = bredMax(v);
    float e = __expf(v - m);
    float Z = bredSum(e);
    g_p[r * 256 + threadIdx.x] = e / Z;
    hid[r * 256 + threadIdx.x] = (v - m) - __logf(Z);
}
__global__ void k_softmax_w(const float* __restrict__ x) {
    int r = blockIdx.x;
    float v = x[r * 64 + threadIdx.x];
    float m = bredMax(v);
    float e = __expf(v - m);
    float Z = bredSum(e);
    g_w[r * 64 + threadIdx.x] = e / Z;
}
__global__ void k_Erow(const float* __restrict__ x, const float* __restrict__ mask) {
    int s = blockIdx.x;
    const float* xr = x + (size_t)s * 2000;
    const float* mr = mask + (size_t)s * 2000;
    float* Er = g_E + (size_t)s * 2000;
    float m = -3.402823e38f;
    for (int n = threadIdx.x; n < 2000; n += 256)
        if (mr[n] > 0.f) m = fmaxf(m, xr[n]);
    m = bredMax(m);
    float sloc = 0.f;
    for (int n = threadIdx.x; n < 2000; n += 256) {
        float e = (mr[n] > 0.f) ? __expf(xr[n] - m) * mr[n] : 0.f;
        Er[n] = e;
        sloc += e;
    }
    float Z = bredSum(sloc);
    float inv = 1.f / Z;
    for (int n = threadIdx.x; n < 2000; n += 256) Er[n] *= inv;
}
__global__ void k_Ecol() {
    int n = blockIdx.x * 256 + threadIdx.x;
    if (n >= 2000) return;
    float m = 0.f;
    for (int s = 0; s < 256; s++) m = fmaxf(m, g_E[(size_t)s * 2000 + n]);
    g_bmaxE[n] = __logf(m);
    float inv = 1.f / m;
    for (int s = 0; s < 256; s++) g_E[(size_t)s * 2000 + n] *= inv;
}
// Et[n][s] = Ee[s][n], zero-padded to n<2048
__global__ void k_transposeE() {
    int n = blockIdx.x, s = threadIdx.x;
    g_Et[(size_t)n * 256 + s] = (n < 2000) ? g_E[(size_t)s * 2000 + n] : 0.f;
}

// ================= SIMT 64x64xK=256 GEMM core (macro body) =================
#define GEMM_BODY(Aexpr, Bexpr)                                                       \
    __shared__ float As[64][68];                                                      \
    __shared__ float Bs[64][68];                                                      \
    const int u = threadIdx.x;                                                        \
    const int tx = u & 15, ty = u >> 4;                                               \
    float acc[4][4];                                                                  \
    _Pragma("unroll") for (int i = 0; i < 4; i++)                                     \
        _Pragma("unroll") for (int j = 0; j < 4; j++) acc[i][j] = 0.f;                \
    for (int k0 = 0; k0 < 256; k0 += 64) {                                            \
        _Pragma("unroll") for (int q = 0; q < 4; q++) {                               \
            int f = q * 256 + u;                                                      \
            int row = f >> 4, kq = (f & 15) << 2;                                     \
            *(float4*)&As[row][kq] = *(const float4*)&(Aexpr);                        \
            *(float4*)&Bs[row][kq] = *(const float4*)&(Bexpr);                        \
        }                                                                             \
        __syncthreads();                                                              \
        _Pragma("unroll") for (int k2 = 0; k2 < 64; k2++) {                           \
            float a0 = As[ty * 4 + 0][k2], a1 = As[ty * 4 + 1][k2];                   \
            float a2 = As[ty * 4 + 2][k2], a3 = As[ty * 4 + 3][k2];                   \
            float4 b = *(const float4*)&Bs[k2][tx * 4];                               \
            acc[0][0] += a0 * b.x; acc[0][1] += a0 * b.y; acc[0][2] += a0 * b.z; acc[0][3] += a0 * b.w; \
            acc[1][0] += a1 * b.x; acc[1][1] += a1 * b.y; acc[1][2] += a1 * b.z; acc[1][3] += a1 * b.w; \
            acc[2][0] += a2 * b.x; acc[2][1] += a2 * b.y; acc[2][2] += a2 * b.z; acc[2][3] += a2 * b.w; \
            acc[3][0] += a3 * b.x; acc[3][1] += a3 * b.y; acc[3][2] += a3 * b.z; acc[3][3] += a3 * b.w; \
        }                                                                             \
        __syncthreads();                                                              \
    }

// Batched power: Ppow[dst+z] = Ppow[src+z] @ Ppow[pw]   (grid: 4 x 4 x count)
__global__ __launch_bounds__(256) void k_pmul(int dst, int src, int pw) {
    const int z = blockIdx.z;
    const float* A = g_Ppow + (size_t)(src + z) * 65536;
    const float* B = g_Ppow + (size_t)pw * 65536;
    float* Cm = g_Ppow + (size_t)(dst + z) * 65536;
    const int r0 = blockIdx.y * 64, c0 = blockIdx.x * 64;
    GEMM_BODY(A[(size_t)(r0 + row) * 256 + k0 + kq],
              B[(size_t)(k0 + row) * 256 + c0 + kq])
#pragma unroll
    for (int i = 0; i < 4; i++)
        *(float4*)&Cm[(size_t)(r0 + ty * 4 + i) * 256 + c0 + tx * 4] =
            make_float4(acc[i][0], acc[i][1], acc[i][2], acc[i][3]);
}

// Backbone: p[64k] = p[64(k-1)] @ P^64   (grid: 4 x 1)
__global__ __launch_bounds__(256) void k_bb(int k) {
    const float* A = g_p + (size_t)(k - 1) * 64 * 16384;
    const float* B = g_Ppow + (size_t)63 * 65536;
    float* Cm = g_p + (size_t)k * 64 * 16384;
    const int c0 = blockIdx.x * 64;
    GEMM_BODY(A[(size_t)row * 256 + k0 + kq],
              B[(size_t)(k0 + row) * 256 + c0 + kq])
#pragma unroll
    for (int i = 0; i < 4; i++)
        *(float4*)&Cm[(size_t)(ty * 4 + i) * 256 + c0 + tx * 4] =
            make_float4(acc[i][0], acc[i][1], acc[i][2], acc[i][3]);
}

// Fill: for t = blockIdx.y+1, p_t = p_base @ P^i, and hid = log(p_t)  (grid: 4 x 499)
__global__ __launch_bounds__(256) void k_fill(float* __restrict__ hid) {
    const int t = blockIdx.y + 1;
    const int base = ((t - 1) >> 6) << 6;
    const int i = t - base;
    const float* A = g_p + (size_t)base * 16384;
    const float* B = g_Ppow + (size_t)(i - 1) * 65536;
    const int c0 = blockIdx.x * 64;
    GEMM_BODY(A[(size_t)row * 256 + k0 + kq],
              B[(size_t)(k0 + row) * 256 + c0 + kq])
    float* pout = g_p + (size_t)t * 16384;
    float* hout = hid + (size_t)t * 16384;
#pragma unroll
    for (int a = 0; a < 4; a++) {
        size_t idx = (size_t)(ty * 4 + a) * 256 + c0 + tx * 4;
        float4 v = make_float4(acc[a][0], acc[a][1], acc[a][2], acc[a][3]);
        *(float4*)&pout[idx] = v;
        *(float4*)&hout[idx] = make_float4(__logf(v.x), __logf(v.y), __logf(v.z), __logf(v.w));
    }
}

// wp[t,s] = sum_c w[t,c] * p_t[c,s]   (grid: 500, block: 256)
__global__ void k_wsum() {
    int t = blockIdx.x, s = threadIdx.x;
    const float* p = g_p + (size_t)t * 16384;
    float a = 0.f;
#pragma unroll 8
    for (int c = 0; c < 64; c++) a += g_w[t * 64 + c] * p[c * 256 + s];
    g_wp[(size_t)t * 256 + s] = a;
}

// ================= emission GEMM via mma.sync tf32 (sm_80+ path) =================
__device__ __forceinline__ void mma_tf32(float* c, const uint32_t* a, const uint32_t* b) {
    asm volatile(
        "mma.sync.aligned.m16n8k8.row.col.f32.tf32.tf32.f32 "
        "{%0,%1,%2,%3}, {%4,%5,%6,%7}, {%8,%9}, {%0,%1,%2,%3};"
        : "+f"(c[0]), "+f"(c[1]), "+f"(c[2]), "+f"(c[3])
        : "r"(a[0]), "r"(a[1]), "r"(a[2]), "r"(a[3]), "r"(b[0]), "r"(b[1]));
}

// D[128,128] = p_rows[128,256] @ Et_rows[128,256]^T
// grid: (16 N-tiles, 250 M-tiles), 256 threads = 8 warps (4 M-groups x 2 N-groups)
__global__ __launch_bounds__(256) void k_emis_mma(float* __restrict__ out) {
    __shared__ float sA[128][36];   // A chunk: rows x k32
    __shared__ float sB[128][36];   // B chunk: cols(n) x k32
    __shared__ float sBM[128];

    const int u = threadIdx.x;
    const int lane = u & 31;
    const int w = u >> 5;
    const int wm = w & 3;       // M group (32 rows)
    const int wn = w >> 2;      // N group (64 cols)
    const int n0 = blockIdx.x * 128;
    const int r0 = blockIdx.y * 128;

    if (u < 128) sBM[u] = g_bmaxE[n0 + u];

    float acc[2][8][4];
#pragma unroll
    for (int mt = 0; mt < 2; mt++)
#pragma unroll
        for (int nt = 0; nt < 8; nt++)
#pragma unroll
            for (int r = 0; r < 4; r++) acc[mt][nt][r] = 0.f;

    const int lr = lane >> 2;       // 0..7
    const int lc = lane & 3;        // 0..3

    for (int ch = 0; ch < 8; ch++) {
        const int k0 = ch * 32;
        // load A/B chunks (each thread: 4 float4 per matrix)
#pragma unroll
        for (int q = 0; q < 4; q++) {
            int f = q * 256 + u;            // 0..1023
            int row = f >> 3, c4 = (f & 7) << 2;
            *(float4*)&sA[row][c4] = *(const float4*)&g_p[(size_t)(r0 + row) * 256 + k0 + c4];
            *(float4*)&sB[row][c4] = *(const float4*)&g_Et[(size_t)(n0 + row) * 256 + k0 + c4];
        }
        __syncthreads();
#pragma unroll
        for (int k8 = 0; k8 < 4; k8++) {
            const int kb = k8 * 8;
            uint32_t bfr[8][2];
#pragma unroll
            for (int nt = 0; nt < 8; nt++) {
                const int nrow = wn * 64 + nt * 8 + lr;
                bfr[nt][0] = __float_as_uint(sB[nrow][kb + lc]);
                bfr[nt][1] = __float_as_uint(sB[nrow][kb + lc + 4]);
            }
#pragma unroll
            for (int mt = 0; mt < 2; mt++) {
                const int arow = wm * 32 + mt * 16 + lr;
                uint32_t afr[4];
                afr[0] = __float_as_uint(sA[arow][kb + lc]);
                afr[1] = __float_as_uint(sA[arow + 8][kb + lc]);
                afr[2] = __float_as_uint(sA[arow][kb + lc + 4]);
                afr[3] = __float_as_uint(sA[arow + 8][kb + lc + 4]);
#pragma unroll
                for (int nt = 0; nt < 8; nt++) mma_tf32(acc[mt][nt], afr, bfr[nt]);
            }
        }
        __syncthreads();
    }

    // epilogue: c0,c1 at (row = base+lr, col = 2*lc+{0,1}); c2,c3 at row+8
    float* obsp = out + 1000000u;
#pragma unroll
    for (int mt = 0; mt < 2; mt++) {
        const int row = r0 + wm * 32 + mt * 16 + lr;
#pragma unroll
        for (int nt = 0; nt < 8; nt++) {
            const int col = wn * 64 + nt * 8 + 2 * lc;
            const int n = n0 + col;
            if (n < 2000) {
                float2 v0, v1;
                v0.x = __logf(acc[mt][nt][0]) + sBM[col];
                v0.y = __logf(acc[mt][nt][1]) + sBM[col + 1];
                v1.x = __logf(acc[mt][nt][2]) + sBM[col];
                v1.y = __logf(acc[mt][nt][3]) + sBM[col + 1];
                *(float2*)&obsp[(size_t)row * 2000 + n] = v0;
                *(float2*)&obsp[(size_t)(row + 8) * 2000 + n] = v1;
            }
        }
    }
}

// log_obs[t,n] = log( sum_s wp[t,s]*Ee[s,n] ) + bm[n]    (grid: 8 x 63, block: 256)
__global__ __launch_bounds__(256) void k_obs(float* __restrict__ out) {
    __shared__ float wsm[8 * 256];
    const int t0 = blockIdx.y * 8;
    const int n = blockIdx.x * 256 + threadIdx.x;
#pragma unroll
    for (int j = 0; j < 8; j++)
        wsm[j * 256 + threadIdx.x] =
            (t0 + j < 500) ? g_wp[(size_t)(t0 + j) * 256 + threadIdx.x] : 0.f;
    __syncthreads();
    float acc[8];
#pragma unroll
    for (int j = 0; j < 8; j++) acc[j] = 0.f;
    for (int s = 0; s < 256; s++) {
        float e = (n < 2000) ? g_E[(size_t)s * 2000 + n] : 0.f;
#pragma unroll
        for (int j = 0; j < 8; j++) acc[j] += wsm[j * 256 + s] * e;
    }
    if (n < 2000) {
        float bm = g_bmaxE[n];
#pragma unroll
        for (int j = 0; j < 8; j++)
            if (t0 + j < 500) out[(size_t)(t0 + j) * 2000 + n] = __logf(acc[j]) + bm;
    }
}

// ================= launch =================
extern "C" void kernel_launch(void* const* d_in, const int* in_sizes, int n_in,
                              void* d_out, int out_size) {
    const float* usi = (const float*)d_in[0];  // [64,256]
    const float* ucw = (const float*)d_in[1];  // [500,64]
    const float* uem = (const float*)d_in[2];  // [256,2000]
    const float* utm = (const float*)d_in[3];  // [256,256]
    const float* msk = (const float*)d_in[4];  // [256,2000]
    float* out = (float*)d_out;
    float* hid = out + 65000000u;

    k_softmax_P<<<256, 256>>>(utm);
    k_softmax_p0<<<64, 256>>>(usi, hid);
    k_softmax_w<<<500, 64>>>(ucw);
    k_Erow<<<256, 256>>>(uem, msk);
    k_Ecol<<<8, 256>>>();
    k_transposeE<<<2048, 256>>>();

    // P^1..P^64 by batched doubling: Ppow[dst+z] = Ppow[src+z] @ Ppow[pw]
    k_pmul<<<dim3(4, 4, 1), 256>>>(1, 0, 0);     // P^2
    k_pmul<<<dim3(4, 4, 2), 256>>>(2, 0, 1);     // P^3..P^4
    k_pmul<<<dim3(4, 4, 4), 256>>>(4, 0, 3);     // P^5..P^8
    k_pmul<<<dim3(4, 4, 8), 256>>>(8, 0, 7);     // P^9..P^16
    k_pmul<<<dim3(4, 4, 16), 256>>>(16, 0, 15);  // P^17..P^32
    k_pmul<<<dim3(4, 4, 32), 256>>>(32, 0, 31);  // P^33..P^64

    // backbone p at t = 64, 128, ..., 448
    for (int k = 1; k <= 7; k++) k_bb<<<dim3(4, 1), 256>>>(k);

    // all t = 1..499 (recomputes backbone t's identically, also writes hid)
    k_fill<<<dim3(4, 499), 256>>>(hid);

    k_wsum<<<500, 256>>>();
    k_emis_mma<<<dim3(16, 250), 256>>>(out);
    k_obs<<<dim3(8, 63), 256>>>(out);
}

// round 4
// speedup vs baseline: 3.1111x; 1.0861x over previous
#include <cuda_runtime.h>
#include <cstdint>

// Problem dims: C=64, S=256, T=500, N=2000
// Output layout (concatenated, float32):
//   log_obs    [T,N]      at offset 0            (1,000,000)
//   log_obs_   [T,C,N]    at offset 1,000,000    (64,000,000)
//   log_hidden [T,C,S]    at offset 65,000,000   (8,192,000)

static __device__ float g_Ppow[64 * 256 * 256];   // g_Ppow[i] = P^(i+1), i=0..63
static __device__ float g_Ppt[64 * 256 * 256];    // transposed powers: g_Ppt[i][n][k] = P^(i+1)[k][n]
static __device__ float g_p[500 * 64 * 256];      // probabilities p_t  [T][C][S]
static __device__ float g_E[256 * 2000];          // E, then Ee = E/colmax in place
static __device__ float g_Et[2048 * 256];         // Ee transposed [N_pad][S], zero padded
static __device__ float g_bmaxE[2048];            // log(colmax of E)
static __device__ float g_w[500 * 64];            // softmax chain weights
static __device__ float g_wp[500 * 256];          // wp[t,s] = sum_c w[t,c] p_t[c,s]

// ================= block reductions =================
__device__ __forceinline__ float bredMax(float v) {
    __shared__ float sm[8];
    unsigned nw = blockDim.x >> 5;
#pragma unroll
    for (int o = 16; o; o >>= 1) v = fmaxf(v, __shfl_xor_sync(0xffffffffu, v, o));
    if ((threadIdx.x & 31) == 0) sm[threadIdx.x >> 5] = v;
    __syncthreads();
    if (threadIdx.x < 32) {
        v = (threadIdx.x < nw) ? sm[threadIdx.x] : -3.402823e38f;
#pragma unroll
        for (int o = 4; o; o >>= 1) v = fmaxf(v, __shfl_xor_sync(0xffffffffu, v, o));
        if (threadIdx.x == 0) sm[0] = v;
    }
    __syncthreads();
    v = sm[0];
    __syncthreads();
    return v;
}
__device__ __forceinline__ float bredSum(float v) {
    __shared__ float sm[8];
    unsigned nw = blockDim.x >> 5;
#pragma unroll
    for (int o = 16; o; o >>= 1) v += __shfl_xor_sync(0xffffffffu, v, o);
    if ((threadIdx.x & 31) == 0) sm[threadIdx.x >> 5] = v;
    __syncthreads();
    if (threadIdx.x < 32) {
        v = (threadIdx.x < nw) ? sm[threadIdx.x] : 0.f;
#pragma unroll
        for (int o = 4; o; o >>= 1) v += __shfl_xor_sync(0xffffffffu, v, o);
        if (threadIdx.x == 0) sm[0] = v;
    }
    __syncthreads();
    v = sm[0];
    __syncthreads();
    return v;
}

// ================= preprocessing =================
__global__ void k_softmax_P(const float* __restrict__ x) {
    int r = blockIdx.x;
    float v = x[r * 256 + threadIdx.x];
    float m = bredMax(v);
    float e = __expf(v - m);
    float Z = bredSum(e);
    float p = e / Z;
    g_Ppow[r * 256 + threadIdx.x] = p;
    g_Ppt[threadIdx.x * 256 + r] = p;
}
__global__ void k_softmax_p0(const float* __restrict__ x, float* __restrict__ hid) {
    int r = blockIdx.x;
    float v = x[r * 256 + threadIdx.x];
    float m = bredMax(v);
    float e = __expf(v - m);
    float Z = bredSum(e);
    g_p[r * 256 + threadIdx.x] = e / Z;
    hid[r * 256 + threadIdx.x] = (v - m) - __logf(Z);
}
__global__ void k_softmax_w(const float* __restrict__ x) {
    int r = blockIdx.x;
    float v = x[r * 64 + threadIdx.x];
    float m = bredMax(v);
    float e = __expf(v - m);
    float Z = bredSum(e);
    g_w[r * 64 + threadIdx.x] = e / Z;
}
__global__ void k_Erow(const float* __restrict__ x, const float* __restrict__ mask) {
    int s = blockIdx.x;
    const float* xr = x + (size_t)s * 2000;
    const float* mr = mask + (size_t)s * 2000;
    float* Er = g_E + (size_t)s * 2000;
    float m = -3.402823e38f;
    for (int n = threadIdx.x; n < 2000; n += 256)
        if (mr[n] > 0.f) m = fmaxf(m, xr[n]);
    m = bredMax(m);
    float sloc = 0.f;
    for (int n = threadIdx.x; n < 2000; n += 256) {
        float e = (mr[n] > 0.f) ? __expf(xr[n] - m) * mr[n] : 0.f;
        Er[n] = e;
        sloc += e;
    }
    float Z = bredSum(sloc);
    float inv = 1.f / Z;
    for (int n = threadIdx.x; n < 2000; n += 256) Er[n] *= inv;
}
__global__ void k_Ecol() {
    int n = blockIdx.x * 256 + threadIdx.x;
    if (n >= 2000) return;
    float m = 0.f;
    for (int s = 0; s < 256; s++) m = fmaxf(m, g_E[(size_t)s * 2000 + n]);
    g_bmaxE[n] = __logf(m);
    float inv = 1.f / m;
    for (int s = 0; s < 256; s++) g_E[(size_t)s * 2000 + n] *= inv;
}
__global__ void k_transposeE() {
    int n = blockIdx.x, s = threadIdx.x;
    g_Et[(size_t)n * 256 + s] = (n < 2000) ? g_E[(size_t)s * 2000 + n] : 0.f;
}

// ================= SIMT 64x64xK=256 GEMM core (macro body) =================
#define GEMM_BODY(Aexpr, Bexpr)                                                       \
    __shared__ float As[64][68];                                                      \
    __shared__ float Bs[64][68];                                                      \
    const int u = threadIdx.x;                                                        \
    const int tx = u & 15, ty = u >> 4;                                               \
    float acc[4][4];                                                                  \
    _Pragma("unroll") for (int i = 0; i < 4; i++)                                     \
        _Pragma("unroll") for (int j = 0; j < 4; j++) acc[i][j] = 0.f;                \
    for (int k0 = 0; k0 < 256; k0 += 64) {                                            \
        _Pragma("unroll") for (int q = 0; q < 4; q++) {                               \
            int f = q * 256 + u;                                                      \
            int row = f >> 4, kq = (f & 15) << 2;                                     \
            *(float4*)&As[row][kq] = *(const float4*)&(Aexpr);                        \
            *(float4*)&Bs[row][kq] = *(const float4*)&(Bexpr);                        \
        }                                                                             \
        __syncthreads();                                                              \
        _Pragma("unroll") for (int k2 = 0; k2 < 64; k2++) {                           \
            float a0 = As[ty * 4 + 0][k2], a1 = As[ty * 4 + 1][k2];                   \
            float a2 = As[ty * 4 + 2][k2], a3 = As[ty * 4 + 3][k2];                   \
            float4 b = *(const float4*)&Bs[k2][tx * 4];                               \
            acc[0][0] += a0 * b.x; acc[0][1] += a0 * b.y; acc[0][2] += a0 * b.z; acc[0][3] += a0 * b.w; \
            acc[1][0] += a1 * b.x; acc[1][1] += a1 * b.y; acc[1][2] += a1 * b.z; acc[1][3] += a1 * b.w; \
            acc[2][0] += a2 * b.x; acc[2][1] += a2 * b.y; acc[2][2] += a2 * b.z; acc[2][3] += a2 * b.w; \
            acc[3][0] += a3 * b.x; acc[3][1] += a3 * b.y; acc[3][2] += a3 * b.z; acc[3][3] += a3 * b.w; \
        }                                                                             \
        __syncthreads();                                                              \
    }

// Batched power: Ppow[dst+z] = Ppow[src+z] @ Ppow[pw]; also stores transpose.
__global__ __launch_bounds__(256) void k_pmul(int dst, int src, int pw) {
    const int z = blockIdx.z;
    const float* A = g_Ppow + (size_t)(src + z) * 65536;
    const float* B = g_Ppow + (size_t)pw * 65536;
    float* Cm = g_Ppow + (size_t)(dst + z) * 65536;
    float* Ct = g_Ppt + (size_t)(dst + z) * 65536;
    const int r0 = blockIdx.y * 64, c0 = blockIdx.x * 64;
    GEMM_BODY(A[(size_t)(r0 + row) * 256 + k0 + kq],
              B[(size_t)(k0 + row) * 256 + c0 + kq])
#pragma unroll
    for (int i = 0; i < 4; i++) {
        *(float4*)&Cm[(size_t)(r0 + ty * 4 + i) * 256 + c0 + tx * 4] =
            make_float4(acc[i][0], acc[i][1], acc[i][2], acc[i][3]);
#pragma unroll
        for (int j = 0; j < 4; j++)
            Ct[(size_t)(c0 + tx * 4 + j) * 256 + r0 + ty * 4 + i] = acc[i][j];
    }
}

// Backbone: p[64k] = p[64(k-1)] @ P^64   (grid: 4 x 1) — fp32 for precision
__global__ __launch_bounds__(256) void k_bb(int k) {
    const float* A = g_p + (size_t)(k - 1) * 64 * 16384;
    const float* B = g_Ppow + (size_t)63 * 65536;
    float* Cm = g_p + (size_t)k * 64 * 16384;
    const int c0 = blockIdx.x * 64;
    GEMM_BODY(A[(size_t)row * 256 + k0 + kq],
              B[(size_t)(k0 + row) * 256 + c0 + kq])
#pragma unroll
    for (int i = 0; i < 4; i++)
        *(float4*)&Cm[(size_t)(ty * 4 + i) * 256 + c0 + tx * 4] =
            make_float4(acc[i][0], acc[i][1], acc[i][2], acc[i][3]);
}

// ================= tf32 mma.sync =================
__device__ __forceinline__ void mma_tf32(float* c, const uint32_t* a, const uint32_t* b) {
    asm volatile(
        "mma.sync.aligned.m16n8k8.row.col.f32.tf32.tf32.f32 "
        "{%0,%1,%2,%3}, {%4,%5,%6,%7}, {%8,%9}, {%0,%1,%2,%3};"
        : "+f"(c[0]), "+f"(c[1]), "+f"(c[2]), "+f"(c[3])
        : "r"(a[0]), "r"(a[1]), "r"(a[2]), "r"(a[3]), "r"(b[0]), "r"(b[1]));
}

// Fill via MMA: p_t[64 x 128-tile] = p_base[64,256] @ P^i, hid = log(p_t)
// grid: (2 N-tiles, 499 t), 256 threads = 8 warps (2 M x 4 N)
__global__ __launch_bounds__(256) void k_fill_mma(float* __restrict__ hid) {
    __shared__ float sA[64][36];
    __shared__ float sB[128][36];
    const int u = threadIdx.x;
    const int lane = u & 31;
    const int w = u >> 5;
    const int wm = w & 1;    // 2 M-groups of 32 rows
    const int wn = w >> 1;   // 4 N-groups of 32 cols
    const int t = blockIdx.y + 1;
    const int base = ((t - 1) >> 6) << 6;
    const int i = t - base;
    const float* A = g_p + (size_t)base * 16384;
    const float* Bt = g_Ppt + (size_t)(i - 1) * 65536;
    const int c0 = blockIdx.x * 128;

    float acc[2][4][4];
#pragma unroll
    for (int mt = 0; mt < 2; mt++)
#pragma unroll
        for (int nt = 0; nt < 4; nt++)
#pragma unroll
            for (int r = 0; r < 4; r++) acc[mt][nt][r] = 0.f;

    const int lr = lane >> 2;   // 0..7
    const int lc = lane & 3;    // 0..3

    for (int ch = 0; ch < 8; ch++) {
        const int k0 = ch * 32;
#pragma unroll
        for (int q = 0; q < 2; q++) {
            int f = q * 256 + u;
            int row = f >> 3, c4 = (f & 7) << 2;
            *(float4*)&sA[row][c4] = *(const float4*)&A[(size_t)row * 256 + k0 + c4];
        }
#pragma unroll
        for (int q = 0; q < 4; q++) {
            int f = q * 256 + u;
            int row = f >> 3, c4 = (f & 7) << 2;
            *(float4*)&sB[row][c4] = *(const float4*)&Bt[(size_t)(c0 + row) * 256 + k0 + c4];
        }
        __syncthreads();
#pragma unroll
        for (int k8 = 0; k8 < 4; k8++) {
            const int kb = k8 * 8;
            uint32_t bfr[4][2];
#pragma unroll
            for (int nt = 0; nt < 4; nt++) {
                const int nrow = wn * 32 + nt * 8 + lr;
                bfr[nt][0] = __float_as_uint(sB[nrow][kb + lc]);
                bfr[nt][1] = __float_as_uint(sB[nrow][kb + lc + 4]);
            }
#pragma unroll
            for (int mt = 0; mt < 2; mt++) {
                const int arow = wm * 32 + mt * 16 + lr;
                uint32_t afr[4];
                afr[0] = __float_as_uint(sA[arow][kb + lc]);
                afr[1] = __float_as_uint(sA[arow + 8][kb + lc]);
                afr[2] = __float_as_uint(sA[arow][kb + lc + 4]);
                afr[3] = __float_as_uint(sA[arow + 8][kb + lc + 4]);
#pragma unroll
                for (int nt = 0; nt < 4; nt++) mma_tf32(acc[mt][nt], afr, bfr[nt]);
            }
        }
        __syncthreads();
    }

    float* pout = g_p + (size_t)t * 16384;
    float* hout = hid + (size_t)t * 16384;
#pragma unroll
    for (int mt = 0; mt < 2; mt++) {
        const int row = wm * 32 + mt * 16 + lr;
#pragma unroll
        for (int nt = 0; nt < 4; nt++) {
            const int col = c0 + wn * 32 + nt * 8 + 2 * lc;
            float2 v0 = make_float2(acc[mt][nt][0], acc[mt][nt][1]);
            float2 v1 = make_float2(acc[mt][nt][2], acc[mt][nt][3]);
            *(float2*)&pout[(size_t)row * 256 + col] = v0;
            *(float2*)&pout[(size_t)(row + 8) * 256 + col] = v1;
            *(float2*)&hout[(size_t)row * 256 + col] = make_float2(__logf(v0.x), __logf(v0.y));
            *(float2*)&hout[(size_t)(row + 8) * 256 + col] = make_float2(__logf(v1.x), __logf(v1.y));
        }
    }
}

// wp[t,s] = sum_c w[t,c] * p_t[c,s]   (grid: 500, block: 256)
__global__ void k_wsum() {
    int t = blockIdx.x, s = threadIdx.x;
    const float* p = g_p + (size_t)t * 16384;
    float a = 0.f;
#pragma unroll 8
    for (int c = 0; c < 64; c++) a += g_w[t * 64 + c] * p[c * 256 + s];
    g_wp[(size_t)t * 256 + s] = a;
}

// ================= emission GEMM via mma.sync tf32 =================
// D[128,128] = p_rows[128,256] @ Et_rows[128,256]^T
// grid: (16 N-tiles, 250 M-tiles), 256 threads = 8 warps (4 M x 2 N)
__global__ __launch_bounds__(256) void k_emis_mma(float* __restrict__ out) {
    __shared__ float sA[128][36];
    __shared__ float sB[128][36];
    __shared__ float sBM[128];

    const int u = threadIdx.x;
    const int lane = u & 31;
    const int w = u >> 5;
    const int wm = w & 3;
    const int wn = w >> 2;
    const int n0 = blockIdx.x * 128;
    const int r0 = blockIdx.y * 128;

    if (u < 128) sBM[u] = g_bmaxE[n0 + u];

    float acc[2][8][4];
#pragma unroll
    for (int mt = 0; mt < 2; mt++)
#pragma unroll
        for (int nt = 0; nt < 8; nt++)
#pragma unroll
            for (int r = 0; r < 4; r++) acc[mt][nt][r] = 0.f;

    const int lr = lane >> 2;
    const int lc = lane & 3;

    for (int ch = 0; ch < 8; ch++) {
        const int k0 = ch * 32;
#pragma unroll
        for (int q = 0; q < 4; q++) {
            int f = q * 256 + u;
            int row = f >> 3, c4 = (f & 7) << 2;
            *(float4*)&sA[row][c4] = *(const float4*)&g_p[(size_t)(r0 + row) * 256 + k0 + c4];
            *(float4*)&sB[row][c4] = *(const float4*)&g_Et[(size_t)(n0 + row) * 256 + k0 + c4];
        }
        __syncthreads();
#pragma unroll
        for (int k8 = 0; k8 < 4; k8++) {
            const int kb = k8 * 8;
            uint32_t bfr[8][2];
#pragma unroll
            for (int nt = 0; nt < 8; nt++) {
                const int nrow = wn * 64 + nt * 8 + lr;
                bfr[nt][0] = __float_as_uint(sB[nrow][kb + lc]);
                bfr[nt][1] = __float_as_uint(sB[nrow][kb + lc + 4]);
            }
#pragma unroll
            for (int mt = 0; mt < 2; mt++) {
                const int arow = wm * 32 + mt * 16 + lr;
                uint32_t afr[4];
                afr[0] = __float_as_uint(sA[arow][kb + lc]);
                afr[1] = __float_as_uint(sA[arow + 8][kb + lc]);
                afr[2] = __float_as_uint(sA[arow][kb + lc + 4]);
                afr[3] = __float_as_uint(sA[arow + 8][kb + lc + 4]);
#pragma unroll
                for (int nt = 0; nt < 8; nt++) mma_tf32(acc[mt][nt], afr, bfr[nt]);
            }
        }
        __syncthreads();
    }

    float* obsp = out + 1000000u;
#pragma unroll
    for (int mt = 0; mt < 2; mt++) {
        const int row = r0 + wm * 32 + mt * 16 + lr;
#pragma unroll
        for (int nt = 0; nt < 8; nt++) {
            const int col = wn * 64 + nt * 8 + 2 * lc;
            const int n = n0 + col;
            if (n < 2000) {
                float2 v0, v1;
                v0.x = __logf(acc[mt][nt][0]) + sBM[col];
                v0.y = __logf(acc[mt][nt][1]) + sBM[col + 1];
                v1.x = __logf(acc[mt][nt][2]) + sBM[col];
                v1.y = __logf(acc[mt][nt][3]) + sBM[col + 1];
                *(float2*)&obsp[(size_t)row * 2000 + n] = v0;
                *(float2*)&obsp[(size_t)(row + 8) * 2000 + n] = v1;
            }
        }
    }
}

// log_obs[t,n] = log( sum_s wp[t,s]*Ee[s,n] ) + bm[n]    (grid: 8 x 63, block: 256)
__global__ __launch_bounds__(256) void k_obs(float* __restrict__ out) {
    __shared__ float wsm[8 * 256];
    const int t0 = blockIdx.y * 8;
    const int n = blockIdx.x * 256 + threadIdx.x;
#pragma unroll
    for (int j = 0; j < 8; j++)
        wsm[j * 256 + threadIdx.x] =
            (t0 + j < 500) ? g_wp[(size_t)(t0 + j) * 256 + threadIdx.x] : 0.f;
    __syncthreads();
    float acc[8];
#pragma unroll
    for (int j = 0; j < 8; j++) acc[j] = 0.f;
    for (int s = 0; s < 256; s++) {
        float e = (n < 2000) ? g_E[(size_t)s * 2000 + n] : 0.f;
#pragma unroll
        for (int j = 0; j < 8; j++) acc[j] += wsm[j * 256 + s] * e;
    }
    if (n < 2000) {
        float bm = g_bmaxE[n];
#pragma unroll
        for (int j = 0; j < 8; j++)
            if (t0 + j < 500) out[(size_t)(t0 + j) * 2000 + n] = __logf(acc[j]) + bm;
    }
}

// ================= launch =================
extern "C" void kernel_launch(void* const* d_in, const int* in_sizes, int n_in,
                              void* d_out, int out_size) {
    const float* usi = (const float*)d_in[0];  // [64,256]
    const float* ucw = (const float*)d_in[1];  // [500,64]
    const float* uem = (const float*)d_in[2];  // [256,2000]
    const float* utm = (const float*)d_in[3];  // [256,256]
    const float* msk = (const float*)d_in[4];  // [256,2000]
    float* out = (float*)d_out;
    float* hid = out + 65000000u;

    k_softmax_P<<<256, 256>>>(utm);
    k_softmax_p0<<<64, 256>>>(usi, hid);
    k_softmax_w<<<500, 64>>>(ucw);
    k_Erow<<<256, 256>>>(uem, msk);
    k_Ecol<<<8, 256>>>();
    k_transposeE<<<2048, 256>>>();

    // P^1..P^64 by batched doubling (fp32, also stores transposes)
    k_pmul<<<dim3(4, 4, 1), 256>>>(1, 0, 0);
    k_pmul<<<dim3(4, 4, 2), 256>>>(2, 0, 1);
    k_pmul<<<dim3(4, 4, 4), 256>>>(4, 0, 3);
    k_pmul<<<dim3(4, 4, 8), 256>>>(8, 0, 7);
    k_pmul<<<dim3(4, 4, 16), 256>>>(16, 0, 15);
    k_pmul<<<dim3(4, 4, 32), 256>>>(32, 0, 31);

    // backbone p at t = 64, 128, ..., 448 (fp32)
    for (int k = 1; k <= 7; k++) k_bb<<<dim3(4, 1), 256>>>(k);

    // all t = 1..499 via tf32 MMA (writes p and log_hidden)
    k_fill_mma<<<dim3(2, 499), 256>>>(hid);

    k_wsum<<<500, 256>>>();
    k_emis_mma<<<dim3(16, 250), 256>>>(out);
    k_obs<<<dim3(8, 63), 256>>>(out);
}